// round 2
// baseline (speedup 1.0000x reference)
#include <cuda_runtime.h>
#include <math.h>

#define BB   2
#define SS   2048
#define DD   768
#define HH   12
#define DH   64
#define TT   64
#define RR   50
#define MR   (BB*SS)      /* 4096 rows */
#define FF   3072

// ---------------- scratch (static device allocations, allowed) ----------------
__device__ float g_q   [MR*DD];
__device__ float g_k   [MR*DD];
__device__ float g_v   [MR*DD];
__device__ float g_ctx [MR*DD];
__device__ float g_tmp [MR*DD];
__device__ float g_x1  [MR*DD];
__device__ float g_x2  [MR*DD];
__device__ float g_tagk[TT*DD];
__device__ float g_tagv[TT*DD];
__device__ float g_int [MR*FF];

// ---------------- SGEMM: C = A[MxK] @ W[KxN] + bias (+epilogue) ----------------
// EPI: 0 = bias, 1 = bias + exact gelu, 2 = bias + residual
template<int EPI>
__global__ __launch_bounds__(256) void sgemm_kernel(
    const float* __restrict__ A, const float* __restrict__ W,
    const float* __restrict__ bias, const float* __restrict__ res,
    float* __restrict__ C, int M, int N, int K)
{
    __shared__ float As[16][64];   // [k][m]
    __shared__ float Bs[16][64];   // [k][n]
    const int tid = threadIdx.x;
    const int tx = tid & 15, ty = tid >> 4;
    const int bn = blockIdx.x * 64, bm = blockIdx.y * 64;

    // A-load mapping: each thread loads a float4 along K
    const int am = tid >> 2;           // 0..63 (row within tile)
    const int ak = (tid & 3) * 4;      // 0,4,8,12
    // W-load mapping: each thread loads a float4 along N
    const int wk = tid >> 4;           // 0..15
    const int wn = (tid & 15) * 4;     // 0..60

    float acc[4][4] = {};

    for (int k0 = 0; k0 < K; k0 += 16) {
        float4 av = *(const float4*)&A[(size_t)(bm + am) * K + k0 + ak];
        As[ak + 0][am] = av.x; As[ak + 1][am] = av.y;
        As[ak + 2][am] = av.z; As[ak + 3][am] = av.w;
        *(float4*)&Bs[wk][wn] = *(const float4*)&W[(size_t)(k0 + wk) * N + bn + wn];
        __syncthreads();
        #pragma unroll
        for (int kk = 0; kk < 16; kk++) {
            float4 a4 = *(const float4*)&As[kk][ty * 4];
            float4 b4 = *(const float4*)&Bs[kk][tx * 4];
            float a[4] = {a4.x, a4.y, a4.z, a4.w};
            float b[4] = {b4.x, b4.y, b4.z, b4.w};
            #pragma unroll
            for (int i = 0; i < 4; i++)
                #pragma unroll
                for (int j = 0; j < 4; j++)
                    acc[i][j] = fmaf(a[i], b[j], acc[i][j]);
        }
        __syncthreads();
    }

    #pragma unroll
    for (int i = 0; i < 4; i++) {
        const int m = bm + ty * 4 + i;
        #pragma unroll
        for (int j = 0; j < 4; j++) {
            const int n = bn + tx * 4 + j;
            float v = acc[i][j] + bias[n];
            if (EPI == 1) v = 0.5f * v * (1.0f + erff(v * 0.70710678118654752f));
            if (EPI == 2) v += res[(size_t)m * N + n];
            C[(size_t)m * N + n] = v;
        }
    }
}

// ---------------- flash attention (64-query tile, online softmax) ----------------
// Layouts: Q [B,S,D] (D = H*DH). KV rows have stride DD; kv_bstride selects the
// batch offset (S*D for self-attn, 0 for shared tag KV). band adds +1 inside
// |q_idx - k_idx| <= RR (additive bias, NOT a hard mask).
__global__ __launch_bounds__(256) void attn_kernel(
    const float* __restrict__ Q, const float* __restrict__ K,
    const float* __restrict__ V, float* __restrict__ O,
    int Skv, long long kv_bstride, int band)
{
    __shared__ float Qs[64][64];   // [dh][q]   (transposed)
    __shared__ float KP[64][64];   // phase 1: K as [dh][k]; phase 2: P as [k][q]
    __shared__ float Vs[64][64];   // [k][dh]
    const int tid = threadIdx.x;
    const int tx = tid & 15, ty = tid >> 4;
    const int qt = blockIdx.x * 64, h = blockIdx.y, b = blockIdx.z;

    const float* qbase = Q + ((size_t)b * SS + qt) * DD + h * DH;
    const float* kbase = K + (size_t)b * kv_bstride + h * DH;
    const float* vbase = V + (size_t)b * kv_bstride + h * DH;

    const int lr = tid >> 2;          // 0..63 row
    const int lc = (tid & 3) * 4;     // base col

    // load Q tile, transposed + pre-scaled by 1/sqrt(DH)
    #pragma unroll
    for (int u = 0; u < 4; u++) {
        const int c = lc + u * 16;
        float4 qv = *(const float4*)&qbase[(size_t)lr * DD + c];
        Qs[c + 0][lr] = qv.x * 0.125f; Qs[c + 1][lr] = qv.y * 0.125f;
        Qs[c + 2][lr] = qv.z * 0.125f; Qs[c + 3][lr] = qv.w * 0.125f;
    }

    float m[4], l[4], o[4][4] = {};
    #pragma unroll
    for (int i = 0; i < 4; i++) { m[i] = -1e30f; l[i] = 0.0f; }

    for (int kt = 0; kt < Skv; kt += 64) {
        __syncthreads();   // previous PV readers done with KP/Vs
        #pragma unroll
        for (int u = 0; u < 4; u++) {
            const int c = lc + u * 16;
            float4 kv4 = *(const float4*)&kbase[(size_t)(kt + lr) * DD + c];
            KP[c + 0][lr] = kv4.x; KP[c + 1][lr] = kv4.y;
            KP[c + 2][lr] = kv4.z; KP[c + 3][lr] = kv4.w;
            *(float4*)&Vs[lr][c] = *(const float4*)&vbase[(size_t)(kt + lr) * DD + c];
        }
        __syncthreads();

        // scores: S = (Q/8) . K^T
        float s[4][4] = {};
        #pragma unroll 16
        for (int kk = 0; kk < 64; kk++) {
            float4 a4 = *(const float4*)&Qs[kk][ty * 4];
            float4 b4 = *(const float4*)&KP[kk][tx * 4];
            float a[4] = {a4.x, a4.y, a4.z, a4.w};
            float b[4] = {b4.x, b4.y, b4.z, b4.w};
            #pragma unroll
            for (int i = 0; i < 4; i++)
                #pragma unroll
                for (int j = 0; j < 4; j++)
                    s[i][j] = fmaf(a[i], b[j], s[i][j]);
        }

        if (band) {
            #pragma unroll
            for (int i = 0; i < 4; i++)
                #pragma unroll
                for (int j = 0; j < 4; j++) {
                    const int dq = (qt + ty * 4 + i) - (kt + tx * 4 + j);
                    if ((unsigned)(dq + RR) <= (unsigned)(2 * RR)) s[i][j] += 1.0f;
                }
        }

        // online softmax (rows ty*4+i are spread across the 16-lane tx group)
        #pragma unroll
        for (int i = 0; i < 4; i++) {
            float rm = fmaxf(fmaxf(s[i][0], s[i][1]), fmaxf(s[i][2], s[i][3]));
            #pragma unroll
            for (int off = 1; off < 16; off <<= 1)
                rm = fmaxf(rm, __shfl_xor_sync(0xffffffffu, rm, off, 16));
            const float mn = fmaxf(m[i], rm);
            const float corr = __expf(m[i] - mn);
            float rs = 0.0f;
            #pragma unroll
            for (int j = 0; j < 4; j++) { s[i][j] = __expf(s[i][j] - mn); rs += s[i][j]; }
            #pragma unroll
            for (int off = 1; off < 16; off <<= 1)
                rs += __shfl_xor_sync(0xffffffffu, rs, off, 16);
            l[i] = l[i] * corr + rs;
            m[i] = mn;
            #pragma unroll
            for (int j = 0; j < 4; j++) o[i][j] *= corr;
        }

        __syncthreads();   // everyone done reading KP as K
        #pragma unroll
        for (int i = 0; i < 4; i++)
            #pragma unroll
            for (int j = 0; j < 4; j++)
                KP[tx * 4 + j][ty * 4 + i] = s[i][j];   // P as [k][q]
        __syncthreads();

        // O += P @ V
        #pragma unroll 16
        for (int kk = 0; kk < 64; kk++) {
            float4 p4 = *(const float4*)&KP[kk][ty * 4];
            float4 v4 = *(const float4*)&Vs[kk][tx * 4];
            float p[4] = {p4.x, p4.y, p4.z, p4.w};
            float v[4] = {v4.x, v4.y, v4.z, v4.w};
            #pragma unroll
            for (int i = 0; i < 4; i++)
                #pragma unroll
                for (int j = 0; j < 4; j++)
                    o[i][j] = fmaf(p[i], v[j], o[i][j]);
        }
    }

    #pragma unroll
    for (int i = 0; i < 4; i++) {
        const float inv = 1.0f / l[i];
        const size_t rowoff = ((size_t)b * SS + qt + ty * 4 + i) * DD + h * DH + tx * 4;
        #pragma unroll
        for (int j = 0; j < 4; j++)
            O[rowoff + j] = o[i][j] * inv;
    }
}

// ---------------- row LayerNorm over D=768 ----------------
__global__ __launch_bounds__(256) void ln_kernel(
    const float* __restrict__ X, const float* __restrict__ gg,
    const float* __restrict__ bb, float* __restrict__ Y)
{
    __shared__ float red[9];
    const int row = blockIdx.x, tid = threadIdx.x;
    const float* x = X + (size_t)row * DD;
    float v0 = x[tid], v1 = x[tid + 256], v2 = x[tid + 512];

    float s = v0 + v1 + v2;
    #pragma unroll
    for (int off = 16; off; off >>= 1) s += __shfl_xor_sync(0xffffffffu, s, off);
    if ((tid & 31) == 0) red[tid >> 5] = s;
    __syncthreads();
    if (tid == 0) { float t = 0; for (int i = 0; i < 8; i++) t += red[i]; red[8] = t; }
    __syncthreads();
    const float mean = red[8] * (1.0f / 768.0f);

    float d0 = v0 - mean, d1 = v1 - mean, d2 = v2 - mean;
    float s2 = d0 * d0 + d1 * d1 + d2 * d2;
    #pragma unroll
    for (int off = 16; off; off >>= 1) s2 += __shfl_xor_sync(0xffffffffu, s2, off);
    __syncthreads();
    if ((tid & 31) == 0) red[tid >> 5] = s2;
    __syncthreads();
    if (tid == 0) { float t = 0; for (int i = 0; i < 8; i++) t += red[i]; red[8] = t; }
    __syncthreads();
    const float rstd = rsqrtf(red[8] * (1.0f / 768.0f) + 1e-12f);

    float* y = Y + (size_t)row * DD;
    y[tid]       = d0 * rstd * gg[tid]       + bb[tid];
    y[tid + 256] = d1 * rstd * gg[tid + 256] + bb[tid + 256];
    y[tid + 512] = d2 * rstd * gg[tid + 512] + bb[tid + 512];
}

// ---------------- host launcher ----------------
extern "C" void kernel_launch(void* const* d_in, const int* in_sizes, int n_in,
                              void* d_out, int out_size)
{
    const float* X      = (const float*)d_in[0];
    const float* tag    = (const float*)d_in[1];
    const float* sa_wq  = (const float*)d_in[2];  const float* sa_bq = (const float*)d_in[3];
    const float* sa_wk  = (const float*)d_in[4];  const float* sa_bk = (const float*)d_in[5];
    const float* sa_wv  = (const float*)d_in[6];  const float* sa_bv = (const float*)d_in[7];
    const float* sa_wo  = (const float*)d_in[8];  const float* sa_bo = (const float*)d_in[9];
    const float* sa_lg  = (const float*)d_in[10]; const float* sa_lb = (const float*)d_in[11];
    const float* ca_wq  = (const float*)d_in[12]; const float* ca_bq = (const float*)d_in[13];
    const float* ca_wk  = (const float*)d_in[14]; const float* ca_bk = (const float*)d_in[15];
    const float* ca_wv  = (const float*)d_in[16]; const float* ca_bv = (const float*)d_in[17];
    const float* ca_wo  = (const float*)d_in[18]; const float* ca_bo = (const float*)d_in[19];
    const float* ca_lg  = (const float*)d_in[20]; const float* ca_lb = (const float*)d_in[21];
    const float* ff_w1  = (const float*)d_in[22]; const float* ff_b1 = (const float*)d_in[23];
    const float* ff_w2  = (const float*)d_in[24]; const float* ff_b2 = (const float*)d_in[25];
    const float* ff_lg  = (const float*)d_in[26]; const float* ff_lb = (const float*)d_in[27];

    float *q, *k, *v, *ctx, *tmp, *x1, *x2, *tk, *tv, *it;
    cudaGetSymbolAddress((void**)&q,   g_q);
    cudaGetSymbolAddress((void**)&k,   g_k);
    cudaGetSymbolAddress((void**)&v,   g_v);
    cudaGetSymbolAddress((void**)&ctx, g_ctx);
    cudaGetSymbolAddress((void**)&tmp, g_tmp);
    cudaGetSymbolAddress((void**)&x1,  g_x1);
    cudaGetSymbolAddress((void**)&x2,  g_x2);
    cudaGetSymbolAddress((void**)&tk,  g_tagk);
    cudaGetSymbolAddress((void**)&tv,  g_tagv);
    cudaGetSymbolAddress((void**)&it,  g_int);

    const dim3 g768(DD / 64, MR / 64);            // (12, 64)
    const dim3 gff (FF / 64, MR / 64);            // (48, 64)
    const dim3 gtag(DD / 64, 1);                  // (12, 1)
    const dim3 gat (SS / 64, HH, BB);             // (32, 12, 2)

    // ---- self attention ----
    sgemm_kernel<0><<<g768, 256>>>(X,  sa_wq, sa_bq, nullptr, q, MR, DD, DD);
    sgemm_kernel<0><<<g768, 256>>>(X,  sa_wk, sa_bk, nullptr, k, MR, DD, DD);
    sgemm_kernel<0><<<g768, 256>>>(X,  sa_wv, sa_bv, nullptr, v, MR, DD, DD);
    attn_kernel<<<gat, 256>>>(q, k, v, ctx, SS, (long long)SS * DD, 1);
    sgemm_kernel<2><<<g768, 256>>>(ctx, sa_wo, sa_bo, X, tmp, MR, DD, DD);
    ln_kernel<<<MR, 256>>>(tmp, sa_lg, sa_lb, x1);

    // ---- cross attention (tags shared across batch) ----
    sgemm_kernel<0><<<g768, 256>>>(x1,  ca_wq, ca_bq, nullptr, q,  MR, DD, DD);
    sgemm_kernel<0><<<gtag, 256>>>(tag, ca_wk, ca_bk, nullptr, tk, TT, DD, DD);
    sgemm_kernel<0><<<gtag, 256>>>(tag, ca_wv, ca_bv, nullptr, tv, TT, DD, DD);
    attn_kernel<<<gat, 256>>>(q, tk, tv, ctx, TT, 0LL, 0);
    sgemm_kernel<2><<<g768, 256>>>(ctx, ca_wo, ca_bo, x1, tmp, MR, DD, DD);
    ln_kernel<<<MR, 256>>>(tmp, ca_lg, ca_lb, x2);

    // ---- FFN ----
    sgemm_kernel<1><<<gff,  256>>>(x2, ff_w1, ff_b1, nullptr, it, MR, FF, DD);
    sgemm_kernel<2><<<g768, 256>>>(it, ff_w2, ff_b2, x2, tmp, MR, DD, FF);
    ln_kernel<<<MR, 256>>>(tmp, ff_lg, ff_lb, (float*)d_out);
}

// round 5
// speedup vs baseline: 1.4757x; 1.4757x over previous
#include <cuda_runtime.h>
#include <math.h>
#include <stdint.h>

#define BB   2
#define SS   2048
#define DD   768
#define HH   12
#define DH   64
#define TT   64
#define RR   50
#define MR   (BB*SS)      /* 4096 rows */
#define FF   3072

// dynamic smem for tgemm: 2 x (A 4096 + B 4096) uints
#define AREG 4096
#define DSMEM_U (4*AREG)
#define DSMEM_B (DSMEM_U*4)

// ---------------- scratch (static device arrays, allowed) ----------------
__device__ float g_q   [MR*DD];
__device__ float g_k   [MR*DD];
__device__ float g_v   [MR*DD];
__device__ float g_ctx [MR*DD];
__device__ float g_tmp [MR*DD];
__device__ float g_x1  [MR*DD];
__device__ float g_x2  [MR*DD];
__device__ float g_tagk[TT*DD];
__device__ float g_tagv[TT*DD];
__device__ float g_int [MR*FF];
__device__ float g_wt  [6*DD*DD + 2*DD*FF];   // transposed weights

static __device__ __forceinline__ uint32_t f2tf32(float x) {
    uint32_t y;
    asm("cvt.rna.tf32.f32 %0, %1;" : "=r"(y) : "f"(x));
    return y;
}

// Stage one 128x32 A chunk + 128x32 B chunk into fragment-permuted smem.
// Layout: A block (m16 x k8) = 128 uints at blk*128, intra-block offset
// (lane*4 + reg) XOR ((blk&7)*4).  B block (n8 x k8) = 64 uints at blk*64,
// offset (lane*2 + reg) XOR ((blk&7)*4).  XOR swizzle cannot leave the block.
static __device__ __forceinline__ void stage_chunk(
    uint32_t* __restrict__ sAp, uint32_t* __restrict__ sBp,
    const float4* ra, const float4* rb, int tid)
{
    #pragma unroll
    for (int u = 0; u < 4; ++u) {
        const int idx  = tid + 256 * u;
        const int row  = idx >> 3;            // 0..127
        const int colb = (idx & 7) * 4;       // 0,4,...,28
        {   // A: fragment m16n8k8, 4 regs/lane
            const int blk   = (row >> 4) * 4 + (colb >> 3);
            const int reg   = ((row & 15) >> 3) + 2 * ((colb & 7) >> 2);
            const int rbase = (row & 7) * 16 + reg;
            const int s     = (blk & 7) * 4;
            const float fv[4] = {ra[u].x, ra[u].y, ra[u].z, ra[u].w};
            #pragma unroll
            for (int i = 0; i < 4; ++i)
                sAp[blk * 128 + ((rbase + i * 4) ^ s)] = f2tf32(fv[i]);
        }
        {   // B: 2 regs/lane
            const int blk   = (row >> 3) * 4 + (colb >> 3);
            const int reg   = (colb & 7) >> 2;
            const int rbase = (row & 7) * 8 + reg;
            const int s     = (blk & 7) * 4;
            const float fv[4] = {rb[u].x, rb[u].y, rb[u].z, rb[u].w};
            #pragma unroll
            for (int i = 0; i < 4; ++i)
                sBp[blk * 64 + ((rbase + i * 2) ^ s)] = f2tf32(fv[i]);
        }
    }
}

// ---------------- weight transpose: W[K,N] -> Wt[N,K] ----------------
__global__ __launch_bounds__(256) void transpose_kernel(
    const float* __restrict__ W, float* __restrict__ Wt, int K, int N)
{
    __shared__ float t[32][33];
    const int kb = blockIdx.y * 32, nb = blockIdx.x * 32;
    const int x = threadIdx.x, y = threadIdx.y;
    #pragma unroll
    for (int dy = 0; dy < 32; dy += 8)
        t[y + dy][x] = W[(size_t)(kb + y + dy) * N + nb + x];
    __syncthreads();
    #pragma unroll
    for (int dy = 0; dy < 32; dy += 8)
        Wt[(size_t)(nb + y + dy) * K + kb + x] = t[x][y + dy];
}

// ---------------- tf32 mma.sync GEMM: C = A[MxK] @ Wt[NxK]^T + bias (+epi) ----------------
// CTA tile 128x128, 8 warps in 2x4, warp tile 64x32 (4x4 m16n8k8 mmas), K chunk 32.
// EPI: 0 = bias, 1 = bias + exact gelu, 2 = bias + residual
template<int EPI>
__global__ __launch_bounds__(256) void tgemm_kernel(
    const float* __restrict__ A, const float* __restrict__ Wt,
    const float* __restrict__ bias, const float* __restrict__ res,
    float* __restrict__ C, int M, int N, int K)
{
    extern __shared__ uint32_t smem_u[];
    uint32_t* sA[2] = { smem_u,            smem_u + AREG     };
    uint32_t* sB[2] = { smem_u + 2*AREG,   smem_u + 3*AREG   };

    const int tid  = threadIdx.x;
    const int wid  = tid >> 5, lane = tid & 31;
    const int bn   = blockIdx.x * 128, bm = blockIdx.y * 128;
    const int wm16 = (wid >> 2) * 4;      // warp's base m16-tile (0 or 4)
    const int wn8  = (wid & 3) * 4;       // warp's base n8-tile (0,4,8,12)

    float acc[4][4][4] = {};
    float4 ra[4], rb[4];

    const int NC = K / 32;

    // ---- stage 0 ----
    #pragma unroll
    for (int u = 0; u < 4; ++u) {
        const int idx = tid + 256 * u;
        const int row = idx >> 3, col = (idx & 7) * 4;
        ra[u] = *(const float4*)&A [(size_t)(bm + row) * K + col];
        rb[u] = *(const float4*)&Wt[(size_t)(bn + row) * K + col];
    }
    stage_chunk(sA[0], sB[0], ra, rb, tid);
    __syncthreads();

    for (int c = 0; c < NC; ++c) {
        const int p = c & 1;
        if (c + 1 < NC) {
            const int k0 = (c + 1) * 32;
            #pragma unroll
            for (int u = 0; u < 4; ++u) {
                const int idx = tid + 256 * u;
                const int row = idx >> 3, col = (idx & 7) * 4;
                ra[u] = *(const float4*)&A [(size_t)(bm + row) * K + k0 + col];
                rb[u] = *(const float4*)&Wt[(size_t)(bn + row) * K + k0 + col];
            }
        }
        // ---- compute on buffer p ----
        #pragma unroll
        for (int k8 = 0; k8 < 4; ++k8) {
            uint4 af[4]; uint2 bf[4];
            #pragma unroll
            for (int t = 0; t < 4; ++t) {
                const int blk = (wm16 + t) * 4 + k8;
                af[t] = *(const uint4*)&sA[p][blk * 128 + ((lane * 4) ^ ((blk & 7) * 4))];
            }
            #pragma unroll
            for (int t = 0; t < 4; ++t) {
                const int blk = (wn8 + t) * 4 + k8;
                bf[t] = *(const uint2*)&sB[p][blk * 64 + ((lane * 2) ^ ((blk & 7) * 4))];
            }
            #pragma unroll
            for (int i = 0; i < 4; ++i)
                #pragma unroll
                for (int j = 0; j < 4; ++j)
                    asm volatile(
                        "mma.sync.aligned.m16n8k8.row.col.f32.tf32.tf32.f32 "
                        "{%0,%1,%2,%3}, {%4,%5,%6,%7}, {%8,%9}, {%0,%1,%2,%3};"
                        : "+f"(acc[i][j][0]), "+f"(acc[i][j][1]),
                          "+f"(acc[i][j][2]), "+f"(acc[i][j][3])
                        : "r"(af[i].x), "r"(af[i].y), "r"(af[i].z), "r"(af[i].w),
                          "r"(bf[j].x), "r"(bf[j].y));
        }
        if (c + 1 < NC) {
            __syncthreads();          // everyone done reading buffer (c+1)&1 from 2 chunks ago
            stage_chunk(sA[(c + 1) & 1], sB[(c + 1) & 1], ra, rb, tid);
            __syncthreads();
        }
    }

    // ---- epilogue: D fragment rows r,(r+8), col pairs ----
    #pragma unroll
    for (int i = 0; i < 4; ++i) {
        const int r0 = bm + (wid >> 2) * 64 + i * 16 + (lane >> 2);
        #pragma unroll
        for (int j = 0; j < 4; ++j) {
            const int cb = bn + (wid & 3) * 32 + j * 8 + (lane & 3) * 2;
            float v0 = acc[i][j][0] + bias[cb];
            float v1 = acc[i][j][1] + bias[cb + 1];
            float v2 = acc[i][j][2] + bias[cb];
            float v3 = acc[i][j][3] + bias[cb + 1];
            if (EPI == 1) {
                v0 = 0.5f * v0 * (1.0f + erff(v0 * 0.70710678118654752f));
                v1 = 0.5f * v1 * (1.0f + erff(v1 * 0.70710678118654752f));
                v2 = 0.5f * v2 * (1.0f + erff(v2 * 0.70710678118654752f));
                v3 = 0.5f * v3 * (1.0f + erff(v3 * 0.70710678118654752f));
            }
            if (EPI == 2) {
                v0 += res[(size_t)r0 * N + cb];
                v1 += res[(size_t)r0 * N + cb + 1];
                v2 += res[(size_t)(r0 + 8) * N + cb];
                v3 += res[(size_t)(r0 + 8) * N + cb + 1];
            }
            *(float2*)&C[(size_t)r0 * N + cb]       = make_float2(v0, v1);
            *(float2*)&C[(size_t)(r0 + 8) * N + cb] = make_float2(v2, v3);
        }
    }
}

// ---------------- small fp32 SGEMM (tag K/V projections only) ----------------
template<int EPI>
__global__ __launch_bounds__(256) void sgemm_kernel(
    const float* __restrict__ A, const float* __restrict__ W,
    const float* __restrict__ bias, const float* __restrict__ res,
    float* __restrict__ C, int M, int N, int K)
{
    __shared__ float As[16][64];
    __shared__ float Bs[16][64];
    const int tid = threadIdx.x;
    const int tx = tid & 15, ty = tid >> 4;
    const int bn = blockIdx.x * 64, bm = blockIdx.y * 64;
    const int am = tid >> 2, ak = (tid & 3) * 4;
    const int wk = tid >> 4, wn = (tid & 15) * 4;
    float acc[4][4] = {};
    for (int k0 = 0; k0 < K; k0 += 16) {
        float4 av = *(const float4*)&A[(size_t)(bm + am) * K + k0 + ak];
        As[ak + 0][am] = av.x; As[ak + 1][am] = av.y;
        As[ak + 2][am] = av.z; As[ak + 3][am] = av.w;
        *(float4*)&Bs[wk][wn] = *(const float4*)&W[(size_t)(k0 + wk) * N + bn + wn];
        __syncthreads();
        #pragma unroll
        for (int kk = 0; kk < 16; kk++) {
            float4 a4 = *(const float4*)&As[kk][ty * 4];
            float4 b4 = *(const float4*)&Bs[kk][tx * 4];
            float a[4] = {a4.x, a4.y, a4.z, a4.w};
            float b[4] = {b4.x, b4.y, b4.z, b4.w};
            #pragma unroll
            for (int i = 0; i < 4; i++)
                #pragma unroll
                for (int j = 0; j < 4; j++)
                    acc[i][j] = fmaf(a[i], b[j], acc[i][j]);
        }
        __syncthreads();
    }
    #pragma unroll
    for (int i = 0; i < 4; i++) {
        const int m = bm + ty * 4 + i;
        #pragma unroll
        for (int j = 0; j < 4; j++) {
            const int n = bn + tx * 4 + j;
            float v = acc[i][j] + bias[n];
            if (EPI == 1) v = 0.5f * v * (1.0f + erff(v * 0.70710678118654752f));
            if (EPI == 2) v += res[(size_t)m * N + n];
            C[(size_t)m * N + n] = v;
        }
    }
}

// ---------------- flash attention (64-query tile, online softmax) ----------------
__global__ __launch_bounds__(256) void attn_kernel(
    const float* __restrict__ Q, const float* __restrict__ K,
    const float* __restrict__ V, float* __restrict__ O,
    int Skv, long long kv_bstride, int band)
{
    __shared__ float Qs[64][64];
    __shared__ float KP[64][64];
    __shared__ float Vs[64][64];
    const int tid = threadIdx.x;
    const int tx = tid & 15, ty = tid >> 4;
    const int qt = blockIdx.x * 64, h = blockIdx.y, b = blockIdx.z;

    const float* qbase = Q + ((size_t)b * SS + qt) * DD + h * DH;
    const float* kbase = K + (size_t)b * kv_bstride + h * DH;
    const float* vbase = V + (size_t)b * kv_bstride + h * DH;

    const int lr = tid >> 2;
    const int lc = (tid & 3) * 4;

    #pragma unroll
    for (int u = 0; u < 4; u++) {
        const int c = lc + u * 16;
        float4 qv = *(const float4*)&qbase[(size_t)lr * DD + c];
        Qs[c + 0][lr] = qv.x * 0.125f; Qs[c + 1][lr] = qv.y * 0.125f;
        Qs[c + 2][lr] = qv.z * 0.125f; Qs[c + 3][lr] = qv.w * 0.125f;
    }

    float m[4], l[4], o[4][4] = {};
    #pragma unroll
    for (int i = 0; i < 4; i++) { m[i] = -1e30f; l[i] = 0.0f; }

    for (int kt = 0; kt < Skv; kt += 64) {
        __syncthreads();
        #pragma unroll
        for (int u = 0; u < 4; u++) {
            const int c = lc + u * 16;
            float4 kv4 = *(const float4*)&kbase[(size_t)(kt + lr) * DD + c];
            KP[c + 0][lr] = kv4.x; KP[c + 1][lr] = kv4.y;
            KP[c + 2][lr] = kv4.z; KP[c + 3][lr] = kv4.w;
            *(float4*)&Vs[lr][c] = *(const float4*)&vbase[(size_t)(kt + lr) * DD + c];
        }
        __syncthreads();

        float s[4][4] = {};
        #pragma unroll 16
        for (int kk = 0; kk < 64; kk++) {
            float4 a4 = *(const float4*)&Qs[kk][ty * 4];
            float4 b4 = *(const float4*)&KP[kk][tx * 4];
            float a[4] = {a4.x, a4.y, a4.z, a4.w};
            float bv[4] = {b4.x, b4.y, b4.z, b4.w};
            #pragma unroll
            for (int i = 0; i < 4; i++)
                #pragma unroll
                for (int j = 0; j < 4; j++)
                    s[i][j] = fmaf(a[i], bv[j], s[i][j]);
        }

        if (band) {
            #pragma unroll
            for (int i = 0; i < 4; i++)
                #pragma unroll
                for (int j = 0; j < 4; j++) {
                    const int dq = (qt + ty * 4 + i) - (kt + tx * 4 + j);
                    if ((unsigned)(dq + RR) <= (unsigned)(2 * RR)) s[i][j] += 1.0f;
                }
        }

        #pragma unroll
        for (int i = 0; i < 4; i++) {
            float rm = fmaxf(fmaxf(s[i][0], s[i][1]), fmaxf(s[i][2], s[i][3]));
            #pragma unroll
            for (int off = 1; off < 16; off <<= 1)
                rm = fmaxf(rm, __shfl_xor_sync(0xffffffffu, rm, off, 16));
            const float mn = fmaxf(m[i], rm);
            const float corr = __expf(m[i] - mn);
            float rs = 0.0f;
            #pragma unroll
            for (int j = 0; j < 4; j++) { s[i][j] = __expf(s[i][j] - mn); rs += s[i][j]; }
            #pragma unroll
            for (int off = 1; off < 16; off <<= 1)
                rs += __shfl_xor_sync(0xffffffffu, rs, off, 16);
            l[i] = l[i] * corr + rs;
            m[i] = mn;
            #pragma unroll
            for (int j = 0; j < 4; j++) o[i][j] *= corr;
        }

        __syncthreads();
        #pragma unroll
        for (int i = 0; i < 4; i++)
            #pragma unroll
            for (int j = 0; j < 4; j++)
                KP[tx * 4 + j][ty * 4 + i] = s[i][j];
        __syncthreads();

        #pragma unroll 16
        for (int kk = 0; kk < 64; kk++) {
            float4 p4 = *(const float4*)&KP[kk][ty * 4];
            float4 v4 = *(const float4*)&Vs[kk][tx * 4];
            float pv[4] = {p4.x, p4.y, p4.z, p4.w};
            float vv[4] = {v4.x, v4.y, v4.z, v4.w};
            #pragma unroll
            for (int i = 0; i < 4; i++)
                #pragma unroll
                for (int j = 0; j < 4; j++)
                    o[i][j] = fmaf(pv[i], vv[j], o[i][j]);
        }
    }

    #pragma unroll
    for (int i = 0; i < 4; i++) {
        const float inv = 1.0f / l[i];
        const size_t rowoff = ((size_t)b * SS + qt + ty * 4 + i) * DD + h * DH + tx * 4;
        #pragma unroll
        for (int j = 0; j < 4; j++)
            O[rowoff + j] = o[i][j] * inv;
    }
}

// ---------------- row LayerNorm over D=768 ----------------
__global__ __launch_bounds__(256) void ln_kernel(
    const float* __restrict__ X, const float* __restrict__ gg,
    const float* __restrict__ bb, float* __restrict__ Y)
{
    __shared__ float red[9];
    const int row = blockIdx.x, tid = threadIdx.x;
    const float* x = X + (size_t)row * DD;
    float v0 = x[tid], v1 = x[tid + 256], v2 = x[tid + 512];

    float s = v0 + v1 + v2;
    #pragma unroll
    for (int off = 16; off; off >>= 1) s += __shfl_xor_sync(0xffffffffu, s, off);
    if ((tid & 31) == 0) red[tid >> 5] = s;
    __syncthreads();
    if (tid == 0) { float t = 0; for (int i = 0; i < 8; i++) t += red[i]; red[8] = t; }
    __syncthreads();
    const float mean = red[8] * (1.0f / 768.0f);

    float d0 = v0 - mean, d1 = v1 - mean, d2 = v2 - mean;
    float s2 = d0 * d0 + d1 * d1 + d2 * d2;
    #pragma unroll
    for (int off = 16; off; off >>= 1) s2 += __shfl_xor_sync(0xffffffffu, s2, off);
    __syncthreads();
    if ((tid & 31) == 0) red[tid >> 5] = s2;
    __syncthreads();
    if (tid == 0) { float t = 0; for (int i = 0; i < 8; i++) t += red[i]; red[8] = t; }
    __syncthreads();
    const float rstd = rsqrtf(red[8] * (1.0f / 768.0f) + 1e-12f);

    float* y = Y + (size_t)row * DD;
    y[tid]       = d0 * rstd * gg[tid]       + bb[tid];
    y[tid + 256] = d1 * rstd * gg[tid + 256] + bb[tid + 256];
    y[tid + 512] = d2 * rstd * gg[tid + 512] + bb[tid + 512];
}

// ---------------- host launcher ----------------
extern "C" void kernel_launch(void* const* d_in, const int* in_sizes, int n_in,
                              void* d_out, int out_size)
{
    const float* X      = (const float*)d_in[0];
    const float* tag    = (const float*)d_in[1];
    const float* sa_wq  = (const float*)d_in[2];  const float* sa_bq = (const float*)d_in[3];
    const float* sa_wk  = (const float*)d_in[4];  const float* sa_bk = (const float*)d_in[5];
    const float* sa_wv  = (const float*)d_in[6];  const float* sa_bv = (const float*)d_in[7];
    const float* sa_wo  = (const float*)d_in[8];  const float* sa_bo = (const float*)d_in[9];
    const float* sa_lg  = (const float*)d_in[10]; const float* sa_lb = (const float*)d_in[11];
    const float* ca_wq  = (const float*)d_in[12]; const float* ca_bq = (const float*)d_in[13];
    const float* ca_wk  = (const float*)d_in[14]; const float* ca_bk = (const float*)d_in[15];
    const float* ca_wv  = (const float*)d_in[16]; const float* ca_bv = (const float*)d_in[17];
    const float* ca_wo  = (const float*)d_in[18]; const float* ca_bo = (const float*)d_in[19];
    const float* ca_lg  = (const float*)d_in[20]; const float* ca_lb = (const float*)d_in[21];
    const float* ff_w1  = (const float*)d_in[22]; const float* ff_b1 = (const float*)d_in[23];
    const float* ff_w2  = (const float*)d_in[24]; const float* ff_b2 = (const float*)d_in[25];
    const float* ff_lg  = (const float*)d_in[26]; const float* ff_lb = (const float*)d_in[27];

    float *q, *k, *v, *ctx, *tmp, *x1, *x2, *tk, *tv, *it, *wt;
    cudaGetSymbolAddress((void**)&q,   g_q);
    cudaGetSymbolAddress((void**)&k,   g_k);
    cudaGetSymbolAddress((void**)&v,   g_v);
    cudaGetSymbolAddress((void**)&ctx, g_ctx);
    cudaGetSymbolAddress((void**)&tmp, g_tmp);
    cudaGetSymbolAddress((void**)&x1,  g_x1);
    cudaGetSymbolAddress((void**)&x2,  g_x2);
    cudaGetSymbolAddress((void**)&tk,  g_tagk);
    cudaGetSymbolAddress((void**)&tv,  g_tagv);
    cudaGetSymbolAddress((void**)&it,  g_int);
    cudaGetSymbolAddress((void**)&wt,  g_wt);

    const size_t WSZ = (size_t)DD * DD;
    float* wtq   = wt;
    float* wtk   = wt + WSZ;
    float* wtv   = wt + 2 * WSZ;
    float* wto   = wt + 3 * WSZ;
    float* wtcq  = wt + 4 * WSZ;
    float* wtcao = wt + 5 * WSZ;
    float* wtff1 = wt + 6 * WSZ;
    float* wtff2 = wtff1 + (size_t)FF * DD;

    cudaFuncSetAttribute((const void*)tgemm_kernel<0>, cudaFuncAttributeMaxDynamicSharedMemorySize, DSMEM_B);
    cudaFuncSetAttribute((const void*)tgemm_kernel<1>, cudaFuncAttributeMaxDynamicSharedMemorySize, DSMEM_B);
    cudaFuncSetAttribute((const void*)tgemm_kernel<2>, cudaFuncAttributeMaxDynamicSharedMemorySize, DSMEM_B);

    // ---- weight transposes ([K,N] -> [N,K]) ----
    const dim3 tb(32, 8);
    transpose_kernel<<<dim3(DD/32, DD/32), tb>>>(sa_wq, wtq,   DD, DD);
    transpose_kernel<<<dim3(DD/32, DD/32), tb>>>(sa_wk, wtk,   DD, DD);
    transpose_kernel<<<dim3(DD/32, DD/32), tb>>>(sa_wv, wtv,   DD, DD);
    transpose_kernel<<<dim3(DD/32, DD/32), tb>>>(sa_wo, wto,   DD, DD);
    transpose_kernel<<<dim3(DD/32, DD/32), tb>>>(ca_wq, wtcq,  DD, DD);
    transpose_kernel<<<dim3(DD/32, DD/32), tb>>>(ca_wo, wtcao, DD, DD);
    transpose_kernel<<<dim3(FF/32, DD/32), tb>>>(ff_w1, wtff1, DD, FF);
    transpose_kernel<<<dim3(DD/32, FF/32), tb>>>(ff_w2, wtff2, FF, DD);

    const dim3 gp (DD / 128, MR / 128);          // (6, 32)
    const dim3 gf (FF / 128, MR / 128);          // (24, 32)
    const dim3 gtag(DD / 64, 1);
    const dim3 gat (SS / 64, HH, BB);

    // ---- self attention ----
    tgemm_kernel<0><<<gp, 256, DSMEM_B>>>(X,  wtq, sa_bq, nullptr, q, MR, DD, DD);
    tgemm_kernel<0><<<gp, 256, DSMEM_B>>>(X,  wtk, sa_bk, nullptr, k, MR, DD, DD);
    tgemm_kernel<0><<<gp, 256, DSMEM_B>>>(X,  wtv, sa_bv, nullptr, v, MR, DD, DD);
    attn_kernel<<<gat, 256>>>(q, k, v, ctx, SS, (long long)SS * DD, 1);
    tgemm_kernel<2><<<gp, 256, DSMEM_B>>>(ctx, wto, sa_bo, X, tmp, MR, DD, DD);
    ln_kernel<<<MR, 256>>>(tmp, sa_lg, sa_lb, x1);

    // ---- cross attention (tags shared across batch) ----
    tgemm_kernel<0><<<gp, 256, DSMEM_B>>>(x1, wtcq, ca_bq, nullptr, q, MR, DD, DD);
    sgemm_kernel<0><<<gtag, 256>>>(tag, ca_wk, ca_bk, nullptr, tk, TT, DD, DD);
    sgemm_kernel<0><<<gtag, 256>>>(tag, ca_wv, ca_bv, nullptr, tv, TT, DD, DD);
    attn_kernel<<<gat, 256>>>(q, tk, tv, ctx, TT, 0LL, 0);
    tgemm_kernel<2><<<gp, 256, DSMEM_B>>>(ctx, wtcao, ca_bo, x1, tmp, MR, DD, DD);
    ln_kernel<<<MR, 256>>>(tmp, ca_lg, ca_lb, x2);

    // ---- FFN ----
    tgemm_kernel<1><<<gf, 256, DSMEM_B>>>(x2, wtff1, ff_b1, nullptr, it, MR, FF, DD);
    tgemm_kernel<2><<<gp, 256, DSMEM_B>>>(it, wtff2, ff_b2, x2, tmp, MR, DD, FF);
    ln_kernel<<<MR, 256>>>(tmp, ff_lg, ff_lb, (float*)d_out);
}